// round 1
// baseline (speedup 1.0000x reference)
#include <cuda_runtime.h>
#include <math.h>

#define NN 2048
#define MM 32
#define JBLK 128                 // threads / j-rows per main block
#define NBLK_X (NN / JBLK)       // 16
#define NPART (NBLK_X * MM)      // 512 partial sums

// ---- scratch (no allocations allowed) ----
__device__ float2 g_s[MM * NN];   // [k][j] -> (ti_normalized, expH)  column-major, interleaved
__device__ float  g_wsum[MM];     // per-column sum of expH
__device__ float  g_part[NPART];  // per-block partial loss sums

// 0.5 * erf Taylor coefficients: phi(d) = 0.5 - d*(C0 + t*(C1 + t*(C2 + t*(C3 + t*C4)))), t = d^2
// valid to ~5e-7 abs for |d| <= 0.3536 (guaranteed by ti normalization)
#define C0  0.5641895835477563f
#define C1 -0.18806319451591878f
#define C2  0.05641895835477563f
#define C3 -0.013433085322565627f
#define C4  0.0026119888127211866f

// ---------------------------------------------------------------------------
// Kernel A: per-column max of (expr - tr), normalized ti, expH, column W sum.
// One block per column, 256 threads, 8 rows/thread.
// ---------------------------------------------------------------------------
__global__ void __launch_bounds__(256) prep_kernel(const float* __restrict__ risk,
                                                   const float* __restrict__ expr,
                                                   const float* __restrict__ tr,
                                                   const float* __restrict__ sigma) {
    const int k   = blockIdx.x;
    const int tid = threadIdx.x;
    __shared__ float red[256];

    float diff[8];
    float mx = -1e30f;
#pragma unroll
    for (int r = 0; r < 8; ++r) {
        int j   = tid + r * 256;
        diff[r] = expr[j * MM + k] - tr[j * MM + k];
        mx      = fmaxf(mx, diff[r]);
    }
    red[tid] = mx;
    __syncthreads();
#pragma unroll
    for (int s = 128; s > 0; s >>= 1) {
        if (tid < s) red[tid] = fmaxf(red[tid], red[tid + s]);
        __syncthreads();
    }
    mx = red[0];
    __syncthreads();

    const float scale = 1.0f / (2.0f * sigma[0] * sqrtf(2.0f));
    float ws = 0.0f;
#pragma unroll
    for (int r = 0; r < 8; ++r) {
        int   j  = tid + r * 256;
        float ti = expf(diff[r] - mx) * scale;       // == exp(diff)/max(exp(diff)) * scale
        float w  = expf(risk[j * MM + k]);
        g_s[k * NN + j] = make_float2(ti, w);        // coalesced (consecutive j per tid)
        ws += w;
    }
    red[tid] = ws;
    __syncthreads();
#pragma unroll
    for (int s = 128; s > 0; s >>= 1) {
        if (tid < s) red[tid] += red[tid + s];
        __syncthreads();
    }
    if (tid == 0) g_wsum[k] = red[0];
}

// ---------------------------------------------------------------------------
// Kernel B: main N x N x M pairwise sum.
// grid (16, 32): blockIdx.y = column k, blockIdx.x = j-chunk of 128 rows.
// Each thread owns one j, loops over all a from shared (broadcast LDS.64).
// phi folded: cumsum = 0.5*(W_k + w_j) - sum_a w_a * d * P(d^2).
// (d==0 at a==j contributes 0, and the reference's diagonal +0.5 is +0.5*w_j.)
// ---------------------------------------------------------------------------
__global__ void __launch_bounds__(JBLK) main_kernel(const float* __restrict__ risk,
                                                    const float* __restrict__ ev) {
    __shared__ float2 s[NN];      // 16 KB: (ti, w) for the whole column
    __shared__ float  wred[JBLK / 32];

    const int k   = blockIdx.y;
    const int tid = threadIdx.x;
    const float2* gs = g_s + k * NN;

    for (int a = tid; a < NN; a += JBLK) s[a] = gs[a];   // coalesced float2 loads
    __syncthreads();

    const int   j   = blockIdx.x * JBLK + tid;
    const float tij = s[j].x;
    const float wj  = s[j].y;

    float S0 = 0.f, S1 = 0.f, S2 = 0.f, S3 = 0.f;
#pragma unroll 2
    for (int a = 0; a < NN; a += 4) {
        float2 x0 = s[a + 0], x1 = s[a + 1], x2 = s[a + 2], x3 = s[a + 3];
        float d0 = tij - x0.x, d1 = tij - x1.x, d2 = tij - x2.x, d3 = tij - x3.x;
        float t0 = d0 * d0, t1 = d1 * d1, t2 = d2 * d2, t3 = d3 * d3;

        float p0 = fmaf(t0, C4, C3);
        float p1 = fmaf(t1, C4, C3);
        float p2 = fmaf(t2, C4, C3);
        float p3 = fmaf(t3, C4, C3);
        p0 = fmaf(t0, p0, C2); p1 = fmaf(t1, p1, C2); p2 = fmaf(t2, p2, C2); p3 = fmaf(t3, p3, C2);
        p0 = fmaf(t0, p0, C1); p1 = fmaf(t1, p1, C1); p2 = fmaf(t2, p2, C1); p3 = fmaf(t3, p3, C1);
        p0 = fmaf(t0, p0, C0); p1 = fmaf(t1, p1, C0); p2 = fmaf(t2, p2, C0); p3 = fmaf(t3, p3, C0);

        S0 = fmaf(x0.y * d0, p0, S0);
        S1 = fmaf(x1.y * d1, p1, S1);
        S2 = fmaf(x2.y * d2, p2, S2);
        S3 = fmaf(x3.y * d3, p3, S3);
    }
    float S   = (S0 + S1) + (S2 + S3);
    float cum = 0.5f * (g_wsum[k] + wj) - S;
    float val = (risk[j * MM + k] - logf(cum)) * ev[j * MM + k];

    // block reduce (deterministic)
#pragma unroll
    for (int o = 16; o > 0; o >>= 1) val += __shfl_down_sync(0xffffffffu, val, o);
    if ((tid & 31) == 0) wred[tid >> 5] = val;
    __syncthreads();
    if (tid == 0) {
        float b = 0.f;
#pragma unroll
        for (int w = 0; w < JBLK / 32; ++w) b += wred[w];
        g_part[blockIdx.y * NBLK_X + blockIdx.x] = b;
    }
}

// ---------------------------------------------------------------------------
// Kernel C: deterministic final reduction of 512 partials -> -loss
// ---------------------------------------------------------------------------
__global__ void __launch_bounds__(NPART) finish_kernel(float* __restrict__ out) {
    __shared__ float red[NPART];
    const int tid = threadIdx.x;
    red[tid] = g_part[tid];
    __syncthreads();
#pragma unroll
    for (int s = NPART / 2; s > 0; s >>= 1) {
        if (tid < s) red[tid] += red[tid + s];
        __syncthreads();
    }
    if (tid == 0) out[0] = -red[0];
}

extern "C" void kernel_launch(void* const* d_in, const int* in_sizes, int n_in,
                              void* d_out, int out_size) {
    const float* risk  = (const float*)d_in[0];
    const float* expr  = (const float*)d_in[1];
    const float* tr    = (const float*)d_in[2];
    const float* ev    = (const float*)d_in[3];
    const float* sigma = (const float*)d_in[4];
    float* out = (float*)d_out;

    prep_kernel<<<MM, 256>>>(risk, expr, tr, sigma);
    main_kernel<<<dim3(NBLK_X, MM), JBLK>>>(risk, ev);
    finish_kernel<<<1, NPART>>>(out);
}